// round 2
// baseline (speedup 1.0000x reference)
#include <cuda_runtime.h>
#include <math.h>

#define SEQ 12
#define MAX_N 100000

// Inter-layer scratch (allocation-free: __device__ globals)
__device__ float g_h1[MAX_N * 64];
__device__ float g_h2[MAX_N * 64];

// ---- packed f32x2 helpers (Blackwell sm_103a) ----
__device__ __forceinline__ unsigned long long dup_f32(float a) {
    unsigned long long r;
    asm("mov.b64 %0, {%1, %1};" : "=l"(r) : "f"(a));
    return r;
}
__device__ __forceinline__ void ffma2(unsigned long long& d, unsigned long long a,
                                      unsigned long long b) {
    asm("fma.rn.f32x2 %0, %1, %2, %0;" : "+l"(d) : "l"(a), "l"(b));
}
__device__ __forceinline__ float2 unpack2(unsigned long long v) {
    float2 r;
    asm("mov.b64 {%0, %1}, %2;" : "=f"(r.x), "=f"(r.y) : "l"(v));
    return r;
}

// One spiral-conv layer: out[n, 0:C_OUT] = act( gather(h_in, idx[n,:]) @ W + b )
// Thread micro-tile: 4 nodes x 8 outs (packed f32x2 accumulators along out dim).
template <int C_IN, int C_OUT, int THREADS, bool ACT>
__global__ __launch_bounds__(THREADS) void spiral_layer(
    const float* __restrict__ h_in, const int* __restrict__ idx,
    const float* __restrict__ W, const float* __restrict__ bias,
    float* __restrict__ h_out, int n_nodes) {
    constexpr int TX = C_OUT / 8;       // threads along outs
    constexpr int TY = THREADS / TX;    // thread rows (4 nodes each)
    constexpr int TILE_N = TY * 4;      // nodes per block
    constexpr int PAD = 4;
    constexpr int LDA = C_IN + PAD;

    extern __shared__ char smem_raw[];
    float* sA = reinterpret_cast<float*>(smem_raw);                    // [TILE_N][LDA]
    float* sB = sA + TILE_N * LDA;                                     // [C_IN][C_OUT]
    int* sIdx = reinterpret_cast<int*>(sB + C_IN * C_OUT);             // [TILE_N][SEQ]

    const int tid = threadIdx.x;
    const int tx = tid % TX;
    const int ty = tid / TX;
    const int node_base = blockIdx.x * TILE_N;

    // Preload the block's gather indices (guard OOB nodes with idx=0).
    {
        const int lim = n_nodes * SEQ;
        const int gb = node_base * SEQ;
#pragma unroll
        for (int i = tid; i < TILE_N * SEQ; i += THREADS)
            sIdx[i] = (gb + i < lim) ? idx[gb + i] : 0;
    }

    unsigned long long acc[4][4];
#pragma unroll
    for (int i = 0; i < 4; ++i)
#pragma unroll
        for (int p = 0; p < 4; ++p) acc[i][p] = 0ull;

#pragma unroll 1
    for (int s = 0; s < SEQ; ++s) {
        __syncthreads();
        // Gather A tile: TILE_N rows of C_IN floats (float4 per thread).
        {
            constexpr int TPR = C_IN / 4;        // threads per row
            constexpr int RPP = THREADS / TPR;   // rows per pass
            const int rr = tid / TPR;
            const int cc = (tid % TPR) * 4;
#pragma unroll
            for (int r0 = 0; r0 < TILE_N; r0 += RPP) {
                const int r = r0 + rr;
                const int g = sIdx[r * SEQ + s];
                const float4 v =
                    *reinterpret_cast<const float4*>(h_in + (size_t)g * C_IN + cc);
                *reinterpret_cast<float4*>(&sA[r * LDA + cc]) = v;
            }
        }
        // Load W slice for this neighbor: rows [s*C_IN, s*C_IN+C_IN), contiguous.
        {
            const float4* src =
                reinterpret_cast<const float4*>(W + (size_t)s * C_IN * C_OUT);
            float4* dst = reinterpret_cast<float4*>(sB);
#pragma unroll
            for (int i = tid; i < C_IN * C_OUT / 4; i += THREADS) dst[i] = src[i];
        }
        __syncthreads();

#pragma unroll 8
        for (int k = 0; k < C_IN; ++k) {
            const ulonglong2* bk =
                reinterpret_cast<const ulonglong2*>(&sB[k * C_OUT + tx * 8]);
            const ulonglong2 b01 = bk[0];
            const ulonglong2 b23 = bk[1];
#pragma unroll
            for (int i = 0; i < 4; ++i) {
                const unsigned long long a2 = dup_f32(sA[(ty * 4 + i) * LDA + k]);
                ffma2(acc[i][0], a2, b01.x);
                ffma2(acc[i][1], a2, b01.y);
                ffma2(acc[i][2], a2, b23.x);
                ffma2(acc[i][3], a2, b23.y);
            }
        }
    }

    // Epilogue: bias + optional ELU, write 2 float4 per node.
#pragma unroll
    for (int i = 0; i < 4; ++i) {
        const int n = node_base + ty * 4 + i;
        if (n < n_nodes) {
            float o[8];
#pragma unroll
            for (int p = 0; p < 4; ++p) {
                const float2 u = unpack2(acc[i][p]);
                o[2 * p] = u.x;
                o[2 * p + 1] = u.y;
            }
#pragma unroll
            for (int j = 0; j < 8; ++j) {
                float v = o[j] + __ldg(&bias[tx * 8 + j]);
                if (ACT) v = (v > 0.0f) ? v : expm1f(v);
                o[j] = v;
            }
            float4* dst =
                reinterpret_cast<float4*>(h_out + (size_t)n * C_OUT + tx * 8);
            dst[0] = make_float4(o[0], o[1], o[2], o[3]);
            dst[1] = make_float4(o[4], o[5], o[6], o[7]);
        }
    }
}

// Shared-memory byte sizes per config.
template <int C_IN, int C_OUT, int THREADS>
constexpr int smem_bytes() {
    constexpr int TX = C_OUT / 8;
    constexpr int TILE_N = (THREADS / TX) * 4;
    return (TILE_N * (C_IN + 4) + C_IN * C_OUT) * 4 + TILE_N * SEQ * 4;
}

extern "C" void kernel_launch(void* const* d_in, const int* in_sizes, int n_in,
                              void* d_out, int out_size) {
    const float* x = (const float*)d_in[0];    // [N,32,1] contiguous = [N,32]
    const int* idx = (const int*)d_in[1];      // [N,12]
    const float* W0 = (const float*)d_in[2];   // [384,64]
    const float* b0 = (const float*)d_in[3];
    const float* W1 = (const float*)d_in[4];   // [768,64]
    const float* b1 = (const float*)d_in[5];
    const float* W2 = (const float*)d_in[6];   // [768,32]
    const float* b2 = (const float*)d_in[7];
    float* out = (float*)d_out;                // [N,32,1]

    const int n = in_sizes[0] / 32;  // N = 100000
    const int TILE = 128;
    const int grid = (n + TILE - 1) / TILE;

    float *h1, *h2;
    cudaGetSymbolAddress((void**)&h1, g_h1);
    cudaGetSymbolAddress((void**)&h2, g_h2);

    constexpr int S0 = smem_bytes<32, 64, 256>();
    constexpr int S1 = smem_bytes<64, 64, 256>();
    constexpr int S2 = smem_bytes<64, 32, 128>();

    cudaFuncSetAttribute(spiral_layer<32, 64, 256, true>,
                         cudaFuncAttributeMaxDynamicSharedMemorySize, S0);
    cudaFuncSetAttribute(spiral_layer<64, 64, 256, true>,
                         cudaFuncAttributeMaxDynamicSharedMemorySize, S1);
    cudaFuncSetAttribute(spiral_layer<64, 32, 128, false>,
                         cudaFuncAttributeMaxDynamicSharedMemorySize, S2);

    spiral_layer<32, 64, 256, true><<<grid, 256, S0>>>(x, idx, W0, b0, h1, n);
    spiral_layer<64, 64, 256, true><<<grid, 256, S1>>>(h1, idx, W1, b1, h2, n);
    spiral_layer<64, 32, 128, false><<<grid, 128, S2>>>(h2, idx, W2, b2, out, n);
}

// round 3
// speedup vs baseline: 1.4416x; 1.4416x over previous
#include <cuda_runtime.h>
#include <math.h>

#define SEQ 12
#define MAX_N 100000

// Inter-layer scratch (allocation-free: __device__ globals)
__device__ float g_h1[MAX_N * 64];
__device__ float g_h2[MAX_N * 64];

// ---- packed f32x2 helpers (Blackwell sm_103a) ----
__device__ __forceinline__ unsigned long long dup_f32(float a) {
    unsigned long long r;
    asm("mov.b64 %0, {%1, %1};" : "=l"(r) : "f"(a));
    return r;
}
__device__ __forceinline__ void ffma2(unsigned long long& d, unsigned long long a,
                                      unsigned long long b) {
    asm("fma.rn.f32x2 %0, %1, %2, %0;" : "+l"(d) : "l"(a), "l"(b));
}
__device__ __forceinline__ float2 unpack2(unsigned long long v) {
    float2 r;
    asm("mov.b64 {%0, %1}, %2;" : "=f"(r.x), "=f"(r.y) : "l"(v));
    return r;
}

// ---- cp.async helpers ----
__device__ __forceinline__ void cp16(void* smem_dst, const void* gsrc) {
    unsigned sa = (unsigned)__cvta_generic_to_shared(smem_dst);
    asm volatile("cp.async.cg.shared.global [%0], [%1], 16;" ::"r"(sa), "l"(gsrc));
}
__device__ __forceinline__ void cp_commit() {
    asm volatile("cp.async.commit_group;" ::: "memory");
}
__device__ __forceinline__ void cp_wait_all() {
    asm volatile("cp.async.wait_group 0;" ::: "memory");
}

// One spiral-conv layer: out[n, 0:C_OUT] = act( gather(h_in, idx[n,:]) @ W + b )
// Thread micro-tile: 4 nodes (strided by TY) x GRAN*4 outs (packed f32x2 accs).
// Double-buffered cp.async pipeline over the SEQ neighbors.
template <int C_IN, int C_OUT, int GRAN, bool ACT>
__global__ __launch_bounds__(256) void spiral_layer(
    const float* __restrict__ h_in, const int* __restrict__ idx,
    const float* __restrict__ W, const float* __restrict__ bias,
    float* __restrict__ h_out, int n_nodes) {
    constexpr int THREADS = 256;
    constexpr int TX = C_OUT / (4 * GRAN);  // threads along outs (8)
    constexpr int TY = THREADS / TX;        // 32 thread rows
    constexpr int TILE_N = 4 * TY;          // 128 nodes per block
    constexpr int LDA = C_IN + 4;           // floats; LDA % 8 == 4 -> bank stride 4
    constexpr int TPR = C_IN / 4;           // 16B chunks per A row
    constexpr int RPP = THREADS / TPR;      // rows gathered per pass
    constexpr int WQ = C_IN * C_OUT / 4;    // 16B chunks of W slice
    constexpr int ABUF = TILE_N * LDA;      // floats per A buffer
    constexpr int BBUF = C_IN * C_OUT;      // floats per B buffer

    extern __shared__ char smem_raw[];
    float* sA = reinterpret_cast<float*>(smem_raw);    // [2][ABUF]
    float* sB = sA + 2 * ABUF;                          // [2][BBUF]
    int* sIdx = reinterpret_cast<int*>(sB + 2 * BBUF);  // [TILE_N][SEQ]

    const int tid = threadIdx.x;
    const int tx = tid % TX;
    const int ty = tid / TX;
    const int node_base = blockIdx.x * TILE_N;

    // Preload the block's gather indices (guard OOB nodes with idx=0).
    {
        const int lim = n_nodes * SEQ;
        const int gb = node_base * SEQ;
#pragma unroll
        for (int i = tid; i < TILE_N * SEQ; i += THREADS)
            sIdx[i] = (gb + i < lim) ? idx[gb + i] : 0;
    }
    __syncthreads();

    // Gather-issue for neighbor s into buffer buf (async).
    const int rr = tid / TPR;
    const int cc4 = tid % TPR;  // 16B chunk within row
    auto issue = [&](int s, int buf) {
        float* A = sA + buf * ABUF;
        float* B = sB + buf * BBUF;
#pragma unroll
        for (int r0 = 0; r0 < TILE_N; r0 += RPP) {
            const int r = r0 + rr;
            const int g = sIdx[r * SEQ + s];
            cp16(&A[r * LDA + cc4 * 4], h_in + (size_t)g * C_IN + cc4 * 4);
        }
        const float* wsrc = W + (size_t)s * C_IN * C_OUT;
#pragma unroll
        for (int i = tid; i < WQ; i += THREADS) cp16(&B[i * 4], wsrc + i * 4);
        cp_commit();
    };

    issue(0, 0);

    unsigned long long acc[4][2 * GRAN];
#pragma unroll
    for (int i = 0; i < 4; ++i)
#pragma unroll
        for (int p = 0; p < 2 * GRAN; ++p) acc[i][p] = 0ull;

#pragma unroll 1
    for (int s = 0; s < SEQ; ++s) {
        cp_wait_all();
        __syncthreads();
        if (s + 1 < SEQ) issue(s + 1, (s + 1) & 1);

        const float* A = sA + (s & 1) * ABUF;
        const float* B = sB + (s & 1) * BBUF;

#pragma unroll 4
        for (int k0 = 0; k0 < C_IN; k0 += 4) {
            // A: one conflict-free LDS.128 per node (4 k's at once).
            float a4[4][4];
#pragma unroll
            for (int i = 0; i < 4; ++i) {
                const float4 v =
                    *reinterpret_cast<const float4*>(&A[(i * TY + ty) * LDA + k0]);
                a4[i][0] = v.x; a4[i][1] = v.y; a4[i][2] = v.z; a4[i][3] = v.w;
            }
#pragma unroll
            for (int kk = 0; kk < 4; ++kk) {
                unsigned long long a2[4];
#pragma unroll
                for (int i = 0; i < 4; ++i) a2[i] = dup_f32(a4[i][kk]);
                const float* brow = B + (k0 + kk) * C_OUT;
#pragma unroll
                for (int p = 0; p < GRAN; ++p) {
                    // granule (tx + p*TX): banks 4tx..4tx+3 -> conflict-free
                    const ulonglong2 b = *reinterpret_cast<const ulonglong2*>(
                        &brow[(tx + p * TX) * 4]);
#pragma unroll
                    for (int i = 0; i < 4; ++i) {
                        ffma2(acc[i][2 * p], a2[i], b.x);
                        ffma2(acc[i][2 * p + 1], a2[i], b.y);
                    }
                }
            }
        }
    }

    // Epilogue: bias + optional ELU, one float4 per granule per node.
#pragma unroll
    for (int i = 0; i < 4; ++i) {
        const int n = node_base + i * TY + ty;
        if (n < n_nodes) {
#pragma unroll
            for (int p = 0; p < GRAN; ++p) {
                const int col = (tx + p * TX) * 4;
                const float2 u0 = unpack2(acc[i][2 * p]);
                const float2 u1 = unpack2(acc[i][2 * p + 1]);
                float o[4] = {u0.x, u0.y, u1.x, u1.y};
#pragma unroll
                for (int j = 0; j < 4; ++j) {
                    float v = o[j] + __ldg(&bias[col + j]);
                    if (ACT) v = (v > 0.0f) ? v : expm1f(v);
                    o[j] = v;
                }
                *reinterpret_cast<float4*>(h_out + (size_t)n * C_OUT + col) =
                    make_float4(o[0], o[1], o[2], o[3]);
            }
        }
    }
}

template <int C_IN, int C_OUT>
constexpr int smem_bytes() {
    constexpr int TILE_N = 128;
    return (2 * TILE_N * (C_IN + 4) + 2 * C_IN * C_OUT) * 4 + TILE_N * SEQ * 4;
}

extern "C" void kernel_launch(void* const* d_in, const int* in_sizes, int n_in,
                              void* d_out, int out_size) {
    const float* x = (const float*)d_in[0];    // [N,32,1] contiguous = [N,32]
    const int* idx = (const int*)d_in[1];      // [N,12]
    const float* W0 = (const float*)d_in[2];   // [384,64]
    const float* b0 = (const float*)d_in[3];
    const float* W1 = (const float*)d_in[4];   // [768,64]
    const float* b1 = (const float*)d_in[5];
    const float* W2 = (const float*)d_in[6];   // [768,32]
    const float* b2 = (const float*)d_in[7];
    float* out = (float*)d_out;                // [N,32,1]

    const int n = in_sizes[0] / 32;  // N = 100000
    const int TILE = 128;
    const int grid = (n + TILE - 1) / TILE;

    float *h1, *h2;
    cudaGetSymbolAddress((void**)&h1, g_h1);
    cudaGetSymbolAddress((void**)&h2, g_h2);

    constexpr int S0 = smem_bytes<32, 64>();
    constexpr int S1 = smem_bytes<64, 64>();
    constexpr int S2 = smem_bytes<64, 32>();

    cudaFuncSetAttribute(spiral_layer<32, 64, 2, true>,
                         cudaFuncAttributeMaxDynamicSharedMemorySize, S0);
    cudaFuncSetAttribute(spiral_layer<64, 64, 2, true>,
                         cudaFuncAttributeMaxDynamicSharedMemorySize, S1);
    cudaFuncSetAttribute(spiral_layer<64, 32, 1, false>,
                         cudaFuncAttributeMaxDynamicSharedMemorySize, S2);

    spiral_layer<32, 64, 2, true><<<grid, 256, S0>>>(x, idx, W0, b0, h1, n);
    spiral_layer<64, 64, 2, true><<<grid, 256, S1>>>(h1, idx, W1, b1, h2, n);
    spiral_layer<64, 32, 1, false><<<grid, 256, S2>>>(h2, idx, W2, b2, out, n);
}

// round 5
// speedup vs baseline: 1.5817x; 1.0972x over previous
#include <cuda_runtime.h>
#include <math.h>

#define SEQ 12
#define MAX_N 100000

// Inter-layer scratch (allocation-free: __device__ globals)
__device__ float g_h1[MAX_N * 64];
__device__ float g_h2[MAX_N * 64];

// ---- packed f32x2 helpers (Blackwell sm_103a) ----
__device__ __forceinline__ unsigned long long dup_f32(float a) {
    unsigned long long r;
    asm("mov.b64 %0, {%1, %1};" : "=l"(r) : "f"(a));
    return r;
}
__device__ __forceinline__ void ffma2(unsigned long long& d, unsigned long long a,
                                      unsigned long long b) {
    asm("fma.rn.f32x2 %0, %1, %2, %0;" : "+l"(d) : "l"(a), "l"(b));
}
__device__ __forceinline__ float2 unpack2(unsigned long long v) {
    float2 r;
    asm("mov.b64 {%0, %1}, %2;" : "=f"(r.x), "=f"(r.y) : "l"(v));
    return r;
}

// ---- cp.async helpers ----
__device__ __forceinline__ void cp16(void* smem_dst, const void* gsrc) {
    unsigned sa = (unsigned)__cvta_generic_to_shared(smem_dst);
    asm volatile("cp.async.cg.shared.global [%0], [%1], 16;" ::"r"(sa), "l"(gsrc));
}
__device__ __forceinline__ void cp_commit() {
    asm volatile("cp.async.commit_group;" ::: "memory");
}
__device__ __forceinline__ void cp_wait_all() {
    asm volatile("cp.async.wait_group 0;" ::: "memory");
}

// One spiral-conv layer: out[n, 0:C_OUT] = act( gather(h_in, idx[n,:]) @ W + b )
// Thread micro-tile: 8 nodes (strided by TY) x GRAN*4 outs (packed f32x2 accs).
// Double-buffered cp.async pipeline over the SEQ neighbors.
template <int C_IN, int C_OUT, int GRAN, bool ACT>
__global__ __launch_bounds__(128) void spiral_layer(
    const float* __restrict__ h_in, const int* __restrict__ idx,
    const float* __restrict__ W, const float* __restrict__ bias,
    float* __restrict__ h_out, int n_nodes) {
    constexpr int THREADS = 128;
    constexpr int NPT = 8;                   // nodes per thread
    constexpr int TX = C_OUT / (4 * GRAN);   // threads along outs (8)
    constexpr int TY = THREADS / TX;         // 16 thread rows
    constexpr int TILE_N = NPT * TY;         // 128 nodes per block
    constexpr int LDA = C_IN + 4;            // floats; bank stride 4 across ty
    constexpr int TPR = C_IN / 4;            // 16B chunks per A row
    constexpr int RPP = THREADS / TPR;       // rows gathered per pass
    constexpr int WQ = C_IN * C_OUT / 4;     // 16B chunks of W slice
    constexpr int ABUF = TILE_N * LDA;       // floats per A buffer
    constexpr int BBUF = C_IN * C_OUT;       // floats per B buffer

    extern __shared__ char smem_raw[];
    float* sA = reinterpret_cast<float*>(smem_raw);     // [2][ABUF]
    float* sB = sA + 2 * ABUF;                          // [2][BBUF]
    int* sIdx = reinterpret_cast<int*>(sB + 2 * BBUF);  // [TILE_N][SEQ]

    const int tid = threadIdx.x;
    const int tx = tid % TX;
    const int ty = tid / TX;
    const int node_base = blockIdx.x * TILE_N;

    // Preload the block's gather indices (guard OOB nodes with idx=0).
    {
        const int lim = n_nodes * SEQ;
        const int gb = node_base * SEQ;
#pragma unroll
        for (int i = tid; i < TILE_N * SEQ; i += THREADS)
            sIdx[i] = (gb + i < lim) ? idx[gb + i] : 0;
    }
    __syncthreads();

    // Gather-issue for neighbor s into buffer buf (async).
    const int rr = tid / TPR;
    const int cc4 = tid % TPR;  // 16B chunk within row
    auto issue = [&](int s, int buf) {
        float* A = sA + buf * ABUF;
        float* B = sB + buf * BBUF;
#pragma unroll
        for (int r0 = 0; r0 < TILE_N; r0 += RPP) {
            const int r = r0 + rr;
            const int g = sIdx[r * SEQ + s];
            cp16(&A[r * LDA + cc4 * 4], h_in + (size_t)g * C_IN + cc4 * 4);
        }
        const float* wsrc = W + (size_t)s * C_IN * C_OUT;
#pragma unroll
        for (int i = tid; i < WQ; i += THREADS) cp16(&B[i * 4], wsrc + i * 4);
        cp_commit();
    };

    issue(0, 0);

    unsigned long long acc[NPT][2 * GRAN];
#pragma unroll
    for (int i = 0; i < NPT; ++i)
#pragma unroll
        for (int p = 0; p < 2 * GRAN; ++p) acc[i][p] = 0ull;

#pragma unroll 1
    for (int s = 0; s < SEQ; ++s) {
        cp_wait_all();
        __syncthreads();
        if (s + 1 < SEQ) issue(s + 1, (s + 1) & 1);

        const float* A = sA + (s & 1) * ABUF;
        const float* B = sB + (s & 1) * BBUF;

#pragma unroll 2
        for (int k0 = 0; k0 < C_IN; k0 += 4) {
            // A: one conflict-free LDS.128 per node (4 k's at once).
            float4 a4[NPT];
#pragma unroll
            for (int i = 0; i < NPT; ++i)
                a4[i] = *reinterpret_cast<const float4*>(&A[(i * TY + ty) * LDA + k0]);
#pragma unroll
            for (int kk = 0; kk < 4; ++kk) {
                ulonglong2 b[GRAN];
                const float* brow = B + (k0 + kk) * C_OUT;
#pragma unroll
                for (int p = 0; p < GRAN; ++p)
                    b[p] = *reinterpret_cast<const ulonglong2*>(
                        &brow[(tx + p * TX) * 4]);
#pragma unroll
                for (int i = 0; i < NPT; ++i) {
                    const float av = (kk == 0)   ? a4[i].x
                                     : (kk == 1) ? a4[i].y
                                     : (kk == 2) ? a4[i].z
                                                 : a4[i].w;
                    const unsigned long long a2 = dup_f32(av);
#pragma unroll
                    for (int p = 0; p < GRAN; ++p) {
                        ffma2(acc[i][2 * p], a2, b[p].x);
                        ffma2(acc[i][2 * p + 1], a2, b[p].y);
                    }
                }
            }
        }
    }

    // Epilogue: bias + optional ELU, one float4 per granule per node.
#pragma unroll
    for (int i = 0; i < NPT; ++i) {
        const int n = node_base + i * TY + ty;
        if (n < n_nodes) {
#pragma unroll
            for (int p = 0; p < GRAN; ++p) {
                const int col = (tx + p * TX) * 4;
                const float2 u0 = unpack2(acc[i][2 * p]);
                const float2 u1 = unpack2(acc[i][2 * p + 1]);
                float o[4] = {u0.x, u0.y, u1.x, u1.y};
#pragma unroll
                for (int j = 0; j < 4; ++j) {
                    float v = o[j] + __ldg(&bias[col + j]);
                    if (ACT) v = (v > 0.0f) ? v : expm1f(v);
                    o[j] = v;
                }
                *reinterpret_cast<float4*>(h_out + (size_t)n * C_OUT + col) =
                    make_float4(o[0], o[1], o[2], o[3]);
            }
        }
    }
}

template <int C_IN, int C_OUT>
constexpr int smem_bytes() {
    constexpr int TILE_N = 128;
    return (2 * TILE_N * (C_IN + 4) + 2 * C_IN * C_OUT) * 4 + TILE_N * SEQ * 4;
}

extern "C" void kernel_launch(void* const* d_in, const int* in_sizes, int n_in,
                              void* d_out, int out_size) {
    const float* x = (const float*)d_in[0];    // [N,32,1] contiguous = [N,32]
    const int* idx = (const int*)d_in[1];      // [N,12]
    const float* W0 = (const float*)d_in[2];   // [384,64]
    const float* b0 = (const float*)d_in[3];
    const float* W1 = (const float*)d_in[4];   // [768,64]
    const float* b1 = (const float*)d_in[5];
    const float* W2 = (const float*)d_in[6];   // [768,32]
    const float* b2 = (const float*)d_in[7];
    float* out = (float*)d_out;                // [N,32,1]

    const int n = in_sizes[0] / 32;  // N = 100000
    const int TILE = 128;
    const int grid = (n + TILE - 1) / TILE;

    float *h1, *h2;
    cudaGetSymbolAddress((void**)&h1, g_h1);
    cudaGetSymbolAddress((void**)&h2, g_h2);

    constexpr int S0 = smem_bytes<32, 64>();
    constexpr int S1 = smem_bytes<64, 64>();
    constexpr int S2 = smem_bytes<64, 32>();

    cudaFuncSetAttribute(spiral_layer<32, 64, 2, true>,
                         cudaFuncAttributeMaxDynamicSharedMemorySize, S0);
    cudaFuncSetAttribute(spiral_layer<64, 64, 2, true>,
                         cudaFuncAttributeMaxDynamicSharedMemorySize, S1);
    cudaFuncSetAttribute(spiral_layer<64, 32, 1, false>,
                         cudaFuncAttributeMaxDynamicSharedMemorySize, S2);

    spiral_layer<32, 64, 2, true><<<grid, 128, S0>>>(x, idx, W0, b0, h1, n);
    spiral_layer<64, 64, 2, true><<<grid, 128, S1>>>(h1, idx, W1, b1, h2, n);
    spiral_layer<64, 32, 1, false><<<grid, 128, S2>>>(h2, idx, W2, b2, out, n);
}